// round 15
// baseline (speedup 1.0000x reference)
#include <cuda_runtime.h>
#include <cuda_fp16.h>
#include <cstdint>

// ---------------------------------------------------------------------------
// Pipeline (plain fp16 GEMMs + fp16 intermediates; error ~3.3e-4 vs 1e-3):
//   S : x -> fp16                        -> g_Ah [M,192] cols 0..127
//   P : W11 -> fp16; fold D into W12 -> fp16  (one kernel)
//   A : fc11 mma.sync GEMM (K=128) + dnew -> g_dnew [M,64] fp16
//   B : segmented prefix-max over T -> dmg fp16 -> g_Ah cols 128..191
//   C : fc12 mma.sync GEMM (K=192)       -> g_strain fp16 [M,384]
//   T : tail v2 (512 CTAs: batch x point-half, cp.async double-buffered)
//       -> partial fc2 sums g_part[2]; then k_softplus sums + softplus -> out
// R15: single change vs R14 = tail overhaul (2x CTA parallelism via point
// split + overlapped loads). All other kernels byte-identical to R14.
// ---------------------------------------------------------------------------

typedef unsigned long long u64;

#define MM 131072   // 256*512

__device__ __align__(16) __half g_dnew[(size_t)MM * 64];
__device__ __align__(16) __half g_strain[(size_t)MM * 384];
__device__ __align__(16) __half g_Ah[(size_t)MM * 192];
__device__ __align__(16) __half g_Bp[384 * 192];
__device__ __align__(16) __half g_B11[128 * 128];
__device__ __align__(16) float g_part[2][(size_t)MM * 6];

__device__ __forceinline__ uint32_t smem_u32(const void* p) {
    uint32_t a;
    asm("{ .reg .u64 t; cvta.to.shared.u64 t, %1; cvt.u32.u64 %0, t; }" : "=r"(a) : "l"(p));
    return a;
}
__device__ __forceinline__ void cpasync16(uint32_t dst, const void* src) {
    asm volatile("cp.async.ca.shared.global [%0], [%1], 16;" :: "r"(dst), "l"(src) : "memory");
}
__device__ __forceinline__ void cpcommit() {
    asm volatile("cp.async.commit_group;" ::: "memory");
}
template <int N>
__device__ __forceinline__ void cpwait() {
    asm volatile("cp.async.wait_group %0;" :: "n"(N) : "memory");
}
__device__ __forceinline__ void ldsm_x4(uint32_t& r0, uint32_t& r1, uint32_t& r2,
                                        uint32_t& r3, uint32_t addr) {
    asm volatile("ldmatrix.sync.aligned.m8n8.x4.shared.b16 {%0,%1,%2,%3}, [%4];"
                 : "=r"(r0), "=r"(r1), "=r"(r2), "=r"(r3) : "r"(addr));
}
__device__ __forceinline__ void mma16816(float& c0, float& c1, float& c2, float& c3,
                                         uint32_t a0, uint32_t a1, uint32_t a2, uint32_t a3,
                                         uint32_t b0, uint32_t b1) {
    asm volatile("mma.sync.aligned.m16n8k16.row.col.f32.f16.f16.f32 "
                 "{%0,%1,%2,%3}, {%4,%5,%6,%7}, {%8,%9}, {%0,%1,%2,%3};"
                 : "+f"(c0), "+f"(c1), "+f"(c2), "+f"(c3)
                 : "r"(a0), "r"(a1), "r"(a2), "r"(a3), "r"(b0), "r"(b1));
}

#define APITCH 80   // smem row pitch: 64B data + 16B pad (conflict-free ldsm)

// ---------------------------------------------------------------------------
// Kernel S: x -> fp16 -> g_Ah cols [0,128)
// ---------------------------------------------------------------------------
__global__ void k_splitx(const float* __restrict__ x)
{
    int idx = blockIdx.x * 256 + threadIdx.x;     // 0 .. MM*32-1
    int m = idx >> 5, q = (idx & 31) << 2;
    float4 v = *(const float4*)(x + (size_t)m * 128 + q);
    __half h[4];
    h[0] = __float2half(v.x); h[1] = __float2half(v.y);
    h[2] = __float2half(v.z); h[3] = __float2half(v.w);
    *(u64*)(g_Ah + (size_t)m * 192 + q) = *(u64*)h;
}

// ---------------------------------------------------------------------------
// Kernel P: both weight preps. idx < 73728: W12-fold -> g_Bp; else W11 -> g_B11
// ---------------------------------------------------------------------------
__global__ void k_prep(const float* __restrict__ W11, const float* __restrict__ W12)
{
    int t = blockIdx.x * 256 + threadIdx.x;
    if (t < 384 * 192) {
        int n = t / 192, k = t % 192;
        int p3 = (n / 3) * 3, j = n % 3;
        const float C   = 1098.9010989010989f;   // E/(1-nu^2)
        const float CNU = 329.67032967032966f;   // C*nu
        const float CSH = 384.61538461538464f;   // C*(1-nu)/2
        float w;
        if (j == 0)      w = C   * W12[(size_t)p3 * 192 + k] + CNU * W12[(size_t)(p3 + 1) * 192 + k];
        else if (j == 1) w = CNU * W12[(size_t)p3 * 192 + k] + C   * W12[(size_t)(p3 + 1) * 192 + k];
        else             w = CSH * W12[(size_t)n * 192 + k];
        g_Bp[t] = __float2half(w);
    } else {
        int i = t - 384 * 192;
        if (i < 128 * 128) g_B11[i] = __float2half(W11[i]);
    }
}

// ---------------------------------------------------------------------------
// Kernel A: fc11 mma.sync GEMM (exact R12/R14 config). grid (1024): BM=128,
//   BN=128, K=128 (4 stages). 8 warps 2Mx4N -> warp tile 64x32.
// ---------------------------------------------------------------------------
#define FC11_STG  20480
#define FC11_SMEM 61440

__global__ void __launch_bounds__(256, 1) k_fc11_mma(const float* __restrict__ b11)
{
    extern __shared__ char smem[];
    const uint32_t sb = smem_u32(smem);
    const int tid  = threadIdx.x;
    const int lane = tid & 31;
    const int w    = tid >> 5;
    const int wm   = w >> 2;            // 0..1
    const int wn   = w & 3;             // 0..3
    const int g    = lane >> 2;
    const int t4   = lane & 3;
    const int m0   = blockIdx.x << 7;

    __shared__ float b11s[128];
    if (tid < 128) b11s[tid] = b11[tid];

    float acc[4][4][4];
#pragma unroll
    for (int a = 0; a < 4; ++a)
#pragma unroll
        for (int b = 0; b < 4; ++b)
#pragma unroll
            for (int c = 0; c < 4; ++c) acc[a][b][c] = 0.f;

    const int lrow = tid >> 2, lch = tid & 3;

    auto issue = [&](int s) {
        const int kk0 = s << 5;
        uint32_t base = sb + (uint32_t)(s % 3) * FC11_STG;
#pragma unroll
        for (int i = 0; i < 2; ++i) {
            int row = lrow + (i << 6);
            cpasync16(base + row * APITCH + (lch << 4),
                      g_Ah + (size_t)(m0 + row) * 192 + kk0 + (lch << 3));
        }
#pragma unroll
        for (int i = 0; i < 2; ++i) {
            int row = lrow + (i << 6);
            cpasync16(base + 10240 + row * APITCH + (lch << 4),
                      g_B11 + (size_t)row * 128 + kk0 + (lch << 3));
        }
        cpcommit();
    };

    issue(0); issue(1);

    for (int s = 0; s < 4; ++s) {
        if (s < 3) { cpwait<1>(); } else { cpwait<0>(); }
        __syncthreads();
        if (s + 2 < 4) issue(s + 2);

        const uint32_t Ab = sb + (uint32_t)(s % 3) * FC11_STG;
        const uint32_t Bb = Ab + 10240u;
#pragma unroll
        for (int ks = 0; ks < 2; ++ks) {
            const int kk = ks << 4;
            uint32_t a[4][4];
#pragma unroll
            for (int mt = 0; mt < 4; ++mt) {
                int row = wm * 64 + mt * 16 + (lane & 15);
                ldsm_x4(a[mt][0], a[mt][1], a[mt][2], a[mt][3],
                        Ab + row * APITCH + ((kk + ((lane >> 4) << 3)) << 1));
            }
#pragma unroll
            for (int np = 0; np < 2; ++np) {
                int n = wn * 32 + np * 16 + ((lane >> 4) << 3) + (lane & 7);
                uint32_t b0, b1, b2, b3;
                ldsm_x4(b0, b1, b2, b3, Bb + n * APITCH + ((kk + (lane & 8)) << 1));
#pragma unroll
                for (int mt = 0; mt < 4; ++mt) {
                    mma16816(acc[mt][2*np][0], acc[mt][2*np][1], acc[mt][2*np][2], acc[mt][2*np][3],
                             a[mt][0], a[mt][1], a[mt][2], a[mt][3], b0, b1);
                    mma16816(acc[mt][2*np+1][0], acc[mt][2*np+1][1], acc[mt][2*np+1][2], acc[mt][2*np+1][3],
                             a[mt][0], a[mt][1], a[mt][2], a[mt][3], b2, b3);
                }
            }
        }
    }

#pragma unroll
    for (int mt = 0; mt < 4; ++mt)
#pragma unroll
        for (int nn = 0; nn < 4; ++nn) {
            int n = wn * 32 + (nn >> 1) * 16 + (nn & 1) * 8 + 2 * t4;
            float be = b11s[n], bo = b11s[n + 1];
            int r0 = m0 + wm * 64 + mt * 16 + g;
#pragma unroll
            for (int hh = 0; hh < 2; ++hh) {
                float v0 = acc[mt][nn][2 * hh]     + be;
                float v1 = acc[mt][nn][2 * hh + 1] + bo;
                v0 = v0 > 0.f ? v0 : 0.01f * v0;
                v1 = v1 > 0.f ? v1 : 0.01f * v1;
                float jn = fmaxf(v0, 0.f);
                float delta = sqrtf(jn * jn + v1 * v1 + 1e-12f);
                float dn = __fdividef(0.1f * (delta - 0.01f),
                                      fmaxf(delta, 1e-12f) * 0.09f);
                dn = fminf(fmaxf(dn, 0.f), 1.f);
                g_dnew[(size_t)(r0 + 8 * hh) * 64 + (n >> 1)] = __float2half(dn);
            }
        }
}

// ---------------------------------------------------------------------------
// Kernel B: segmented prefix-max (exact R14). grid 256, 512 threads.
// ---------------------------------------------------------------------------
__global__ void __launch_bounds__(512, 2) k_prefixmax()
{
    __shared__ float segmax[8][64];
    const int b = blockIdx.x;
    const int p = threadIdx.x & 63;
    const int s = threadIdx.x >> 6;     // 0..7
    const __half* src = g_dnew + (size_t)b * 512 * 64 + (size_t)s * 64 * 64 + p;

    float mx = 0.f;
    for (int t0 = 0; t0 < 64; t0 += 8) {
        float v[8];
#pragma unroll
        for (int i = 0; i < 8; ++i) v[i] = __half2float(src[(size_t)(t0 + i) * 64]);
#pragma unroll
        for (int i = 0; i < 8; ++i) mx = fmaxf(mx, v[i]);
    }
    segmax[s][p] = mx;
    __syncthreads();

    float run = 0.f;
#pragma unroll
    for (int ss = 0; ss < 7; ++ss)
        if (ss < s) run = fmaxf(run, segmax[ss][p]);

    __half* dh = g_Ah + (size_t)b * 512 * 192 + (size_t)s * 64 * 192 + 128 + p;
    for (int t0 = 0; t0 < 64; t0 += 8) {
        float v[8];
#pragma unroll
        for (int i = 0; i < 8; ++i) v[i] = __half2float(src[(size_t)(t0 + i) * 64]);
#pragma unroll
        for (int i = 0; i < 8; ++i) {
            run = fmaxf(run, v[i]);
            dh[(size_t)(t0 + i) * 192] = __float2half(run);
        }
    }
}

// ---------------------------------------------------------------------------
// Kernel C: fc12 mma.sync GEMM (exact R12/R14 config). grid (4, 1024).
// ---------------------------------------------------------------------------
#define FC12_STG  17920
#define FC12_SMEM 53760

__global__ void __launch_bounds__(256, 2) k_fc12_mma()
{
    extern __shared__ char smem[];
    const uint32_t sb = smem_u32(smem);
    const int tid  = threadIdx.x;
    const int lane = tid & 31;
    const int w    = tid >> 5;
    const int wm   = w >> 1;
    const int wn   = w & 1;
    const int g    = lane >> 2;
    const int t4   = lane & 3;
    const int gy   = blockIdx.x;          // n-tile: cols gy*96..
    const int m0   = blockIdx.y << 7;

    float acc[2][6][4];
#pragma unroll
    for (int a = 0; a < 2; ++a)
#pragma unroll
        for (int b = 0; b < 6; ++b)
#pragma unroll
            for (int c = 0; c < 4; ++c) acc[a][b][c] = 0.f;

    const int lrow = tid >> 2, lch = tid & 3;

    auto issue = [&](int s) {
        const int kk0 = s << 5;
        uint32_t base = sb + (uint32_t)(s % 3) * FC12_STG;
#pragma unroll
        for (int i = 0; i < 2; ++i) {
            int row = lrow + (i << 6);
            cpasync16(base + row * APITCH + (lch << 4),
                      g_Ah + (size_t)(m0 + row) * 192 + kk0 + (lch << 3));
        }
#pragma unroll
        for (int i = 0; i < 2; ++i) {
            int id = tid + (i << 8);
            if (id < 384) {
                int row = id >> 2, c = id & 3;
                cpasync16(base + 10240 + row * APITCH + (c << 4),
                          g_Bp + (size_t)(gy * 96 + row) * 192 + kk0 + (c << 3));
            }
        }
        cpcommit();
    };

    issue(0); issue(1);

    for (int s = 0; s < 6; ++s) {
        if (s < 5) { cpwait<1>(); } else { cpwait<0>(); }
        __syncthreads();
        if (s + 2 < 6) issue(s + 2);

        const uint32_t Ab = sb + (uint32_t)(s % 3) * FC12_STG;
        const uint32_t Bb = Ab + 10240u;
#pragma unroll
        for (int ks = 0; ks < 2; ++ks) {
            const int kk = ks << 4;
            uint32_t a[2][4];
#pragma unroll
            for (int mt = 0; mt < 2; ++mt) {
                int row = wm * 32 + mt * 16 + (lane & 15);
                ldsm_x4(a[mt][0], a[mt][1], a[mt][2], a[mt][3],
                        Ab + row * APITCH + ((kk + ((lane >> 4) << 3)) << 1));
            }
#pragma unroll
            for (int np = 0; np < 3; ++np) {
                int n = wn * 48 + np * 16 + ((lane >> 4) << 3) + (lane & 7);
                uint32_t b0, b1, b2, b3;
                ldsm_x4(b0, b1, b2, b3, Bb + n * APITCH + ((kk + (lane & 8)) << 1));
#pragma unroll
                for (int mt = 0; mt < 2; ++mt) {
                    mma16816(acc[mt][2*np][0], acc[mt][2*np][1], acc[mt][2*np][2], acc[mt][2*np][3],
                             a[mt][0], a[mt][1], a[mt][2], a[mt][3], b0, b1);
                    mma16816(acc[mt][2*np+1][0], acc[mt][2*np+1][1], acc[mt][2*np+1][2], acc[mt][2*np+1][3],
                             a[mt][0], a[mt][1], a[mt][2], a[mt][3], b2, b3);
                }
            }
        }
    }

    const int cb = gy * 96 + wn * 48;
#pragma unroll
    for (int mt = 0; mt < 2; ++mt) {
        int row0 = m0 + wm * 32 + mt * 16 + g;
#pragma unroll
        for (int j = 0; j < 6; ++j) {
            int col = cb + (j >> 1) * 16 + (j & 1) * 8 + 2 * t4;
            __half2 vlo = __floats2half2_rn(acc[mt][j][0], acc[mt][j][1]);
            __half2 vhi = __floats2half2_rn(acc[mt][j][2], acc[mt][j][3]);
            *(__half2*)&g_strain[(size_t)row0 * 384 + col]       = vlo;
            *(__half2*)&g_strain[(size_t)(row0 + 8) * 384 + col] = vhi;
        }
    }
}

// ---------------------------------------------------------------------------
// Kernel T: tail v2. grid (256 batches, 2 point-halves), 128 threads.
//   Each CTA owns points [ph*64, ph*64+64) = sig cols [ph*192, ph*192+192).
//   Double-buffered cp.async chunks (32 t-rows x 192 halves), ep chains on
//   tid<64, partial GEMV over 192 cols -> g_part[ph].
//   smem: w2s [192][8] f32 @0 (6144B), scs [32][64] f32 @6144 (8192B),
//         gs16 2 x (32 rows x 400B) @14336 (25600B). Total 39936B.
// ---------------------------------------------------------------------------
#define T2_W2S   0
#define T2_SCS   6144
#define T2_GS    14336
#define T2_BUFSZ 12800
#define T2_SMEM  39936

__global__ void __launch_bounds__(128, 1) k_tail2(const float* __restrict__ W2,
                                                  float* __restrict__ part0,
                                                  float* __restrict__ part1)
{
    extern __shared__ char ts[];
    const uint32_t sbase = smem_u32(ts);
    float* w2s = (float*)(ts + T2_W2S);      // [192][8]
    float* scs = (float*)(ts + T2_SCS);      // [32][64]
    const int tid = threadIdx.x;
    const int b   = blockIdx.x;
    const int ph  = blockIdx.y;              // 0..1

    // stage W2 slice: rows kg = ph*192 + r
    for (int i = tid; i < 1536; i += 128) {
        int r = i >> 3, o = i & 7;
        w2s[r * 8 + o] = (o < 6) ? W2[(size_t)o * 384 + ph * 192 + r] : 0.f;
    }

    const __half* sigb = g_strain + (size_t)b * 512 * 384 + ph * 192;
    float* part = ph ? part1 : part0;

    auto issue = [&](int c) {
        uint32_t base = sbase + T2_GS + (uint32_t)(c & 1) * T2_BUFSZ;
        const __half* src = sigb + (size_t)c * 32 * 384;
#pragma unroll
        for (int i = 0; i < 6; ++i) {
            int idx = tid + (i << 7);        // 0..767
            int row = idx / 24, ch = idx % 24;
            cpasync16(base + row * 400 + (ch << 4), src + (size_t)row * 384 + (ch << 3));
        }
        cpcommit();
    };

    issue(0);

    const float SY = 10.f, H = 100.f;
    const float INV = (float)(1.0 / (3.0 * (1000.0 / 2.6) + 100.0));
    float ep = 0.f;
    const int tlb = tid >> 2, q = tid & 3;
    const int pp = tid;                      // ep chain point (tid<64)

    for (int c = 0; c < 16; ++c) {
        cpwait<0>();
        __syncthreads();                     // data ready + prior GEMV done
        if (c < 15) issue(c + 1);

        const __half* gbuf = (const __half*)(ts + T2_GS + (c & 1) * T2_BUFSZ);

        if (tid < 64) {
#pragma unroll 4
            for (int tl = 0; tl < 32; ++tl) {
                const __half* row = (const __half*)((const char*)gbuf + tl * 400);
                float s0 = __half2float(row[3 * pp]);
                float s1 = __half2float(row[3 * pp + 1]);
                float s2 = __half2float(row[3 * pp + 2]);
                float seq = sqrtf(s0 * s0 - s0 * s1 + s1 * s1 + 3.f * s2 * s2 + 1e-12f);
                float fy = seq - fmaf(H, ep, SY);
                float sc;
                if (fy > 0.f) {
                    ep = fmaf(fy, INV, ep);
                    sc = __fdividef(fmaf(H, ep, SY), seq);
                } else {
                    sc = 1.f;
                }
                scs[tl * 64 + pp] = sc;
            }
        }
        __syncthreads();

        // partial GEMV: thread (tlb, q) handles k = 4i+q over 192 cols
        float acc[6] = {0.f, 0.f, 0.f, 0.f, 0.f, 0.f};
        const __half* grow = (const __half*)((const char*)gbuf + tlb * 400);
        const float* srow = scs + tlb * 64;
#pragma unroll 8
        for (int i = 0; i < 48; ++i) {
            int k = (i << 2) + q;
            float gv = __half2float(grow[k]) * srow[k / 3];
            float4 wa = *(float4*)&w2s[k * 8];
            float2 wb = *(float2*)&w2s[k * 8 + 4];
            acc[0] = fmaf(gv, wa.x, acc[0]);
            acc[1] = fmaf(gv, wa.y, acc[1]);
            acc[2] = fmaf(gv, wa.z, acc[2]);
            acc[3] = fmaf(gv, wa.w, acc[3]);
            acc[4] = fmaf(gv, wb.x, acc[4]);
            acc[5] = fmaf(gv, wb.y, acc[5]);
        }
#pragma unroll
        for (int o = 0; o < 6; ++o) {
            acc[o] += __shfl_xor_sync(0xffffffffu, acc[o], 1);
            acc[o] += __shfl_xor_sync(0xffffffffu, acc[o], 2);
        }
        if (q == 0) {
            size_t t = (size_t)b * 512 + c * 32 + tlb;
#pragma unroll
            for (int o = 0; o < 6; ++o) part[t * 6 + o] = acc[o];
        }
    }
}

// ---------------------------------------------------------------------------
// Kernel U: sum halves + softplus -> out. MM*6 = 786432 f32 = 196608 float4.
// ---------------------------------------------------------------------------
__global__ void k_softplus(float* __restrict__ out)
{
    int i = blockIdx.x * 256 + threadIdx.x;   // 0..196607 (x4)
    float4 a = *(const float4*)&g_part[0][(size_t)i * 4];
    float4 bq = *(const float4*)&g_part[1][(size_t)i * 4];
    float v[4] = {a.x + bq.x, a.y + bq.y, a.z + bq.z, a.w + bq.w};
    float4 r;
    r.x = fmaxf(v[0], 0.f) + log1pf(expf(-fabsf(v[0])));
    r.y = fmaxf(v[1], 0.f) + log1pf(expf(-fabsf(v[1])));
    r.z = fmaxf(v[2], 0.f) + log1pf(expf(-fabsf(v[2])));
    r.w = fmaxf(v[3], 0.f) + log1pf(expf(-fabsf(v[3])));
    *(float4*)&out[(size_t)i * 4] = r;
}

// ---------------------------------------------------------------------------
extern "C" void kernel_launch(void* const* d_in, const int* in_sizes, int n_in,
                              void* d_out, int out_size)
{
    const float* x   = (const float*)d_in[0];
    const float* W11 = (const float*)d_in[1];
    const float* b11 = (const float*)d_in[2];
    const float* W12 = (const float*)d_in[3];
    const float* W2  = (const float*)d_in[4];
    float* out = (float*)d_out;

    (void)in_sizes; (void)n_in; (void)out_size;

    cudaFuncSetAttribute(k_fc11_mma, cudaFuncAttributeMaxDynamicSharedMemorySize, FC11_SMEM);
    cudaFuncSetAttribute(k_fc12_mma, cudaFuncAttributeMaxDynamicSharedMemorySize, FC12_SMEM);
    cudaFuncSetAttribute(k_tail2,    cudaFuncAttributeMaxDynamicSharedMemorySize, T2_SMEM);

    float* p0;
    float* p1;
    cudaGetSymbolAddress((void**)&p0, g_part);
    p1 = p0 + (size_t)MM * 6;

    k_splitx<<<MM / 8, 256>>>(x);
    k_prep<<<352, 256>>>(W11, W12);
    k_fc11_mma<<<MM / 128, 256, FC11_SMEM>>>(b11);
    k_prefixmax<<<256, 512>>>();
    k_fc12_mma<<<dim3(4, MM / 128), 256, FC12_SMEM>>>();
    k_tail2<<<dim3(256, 2), 128, T2_SMEM>>>(W2, p0, p1);
    k_softplus<<<768, 256>>>(out);
}

// round 16
// speedup vs baseline: 1.0871x; 1.0871x over previous
#include <cuda_runtime.h>
#include <cuda_fp16.h>
#include <cstdint>

// ---------------------------------------------------------------------------
// Pipeline (plain fp16 GEMMs + fp16 intermediates; error ~3.3e-4 vs 1e-3):
//   S : x -> fp16                        -> g_Ah [M,192] cols 0..127
//   P : W11 -> fp16; fold D into W12 -> fp16  (one kernel)
//   A : fc11 mma.sync GEMM (K=128) + dnew -> g_dnew [M,64] fp16
//   B : segmented prefix-max over T -> dmg fp16 -> g_Ah cols 128..191
//   C : fc12 mma.sync GEMM (K=192)       -> g_strain fp16 [M,384]
//   T : fused seq + J2 scan + fc2 + softplus -> out
// R16: exact R14 + ONE change: fc12 epilogue via smem slab -> fully
// coalesced 16B stores (direct half2 stores had ~4x write amplification).
// ---------------------------------------------------------------------------

typedef unsigned long long u64;

#define MM 131072   // 256*512

__device__ __align__(16) __half g_dnew[(size_t)MM * 64];
__device__ __align__(16) __half g_strain[(size_t)MM * 384];
__device__ __align__(16) __half g_Ah[(size_t)MM * 192];
__device__ __align__(16) __half g_Bp[384 * 192];
__device__ __align__(16) __half g_B11[128 * 128];

__device__ __forceinline__ uint32_t smem_u32(const void* p) {
    uint32_t a;
    asm("{ .reg .u64 t; cvta.to.shared.u64 t, %1; cvt.u32.u64 %0, t; }" : "=r"(a) : "l"(p));
    return a;
}
__device__ __forceinline__ void cpasync16(uint32_t dst, const void* src) {
    asm volatile("cp.async.ca.shared.global [%0], [%1], 16;" :: "r"(dst), "l"(src) : "memory");
}
__device__ __forceinline__ void cpcommit() {
    asm volatile("cp.async.commit_group;" ::: "memory");
}
template <int N>
__device__ __forceinline__ void cpwait() {
    asm volatile("cp.async.wait_group %0;" :: "n"(N) : "memory");
}
__device__ __forceinline__ void ldsm_x4(uint32_t& r0, uint32_t& r1, uint32_t& r2,
                                        uint32_t& r3, uint32_t addr) {
    asm volatile("ldmatrix.sync.aligned.m8n8.x4.shared.b16 {%0,%1,%2,%3}, [%4];"
                 : "=r"(r0), "=r"(r1), "=r"(r2), "=r"(r3) : "r"(addr));
}
__device__ __forceinline__ void mma16816(float& c0, float& c1, float& c2, float& c3,
                                         uint32_t a0, uint32_t a1, uint32_t a2, uint32_t a3,
                                         uint32_t b0, uint32_t b1) {
    asm volatile("mma.sync.aligned.m16n8k16.row.col.f32.f16.f16.f32 "
                 "{%0,%1,%2,%3}, {%4,%5,%6,%7}, {%8,%9}, {%0,%1,%2,%3};"
                 : "+f"(c0), "+f"(c1), "+f"(c2), "+f"(c3)
                 : "r"(a0), "r"(a1), "r"(a2), "r"(a3), "r"(b0), "r"(b1));
}

#define APITCH 80   // smem row pitch: 64B data + 16B pad (conflict-free ldsm)

// ---------------------------------------------------------------------------
// Kernel S: x -> fp16 -> g_Ah cols [0,128)
// ---------------------------------------------------------------------------
__global__ void k_splitx(const float* __restrict__ x)
{
    int idx = blockIdx.x * 256 + threadIdx.x;     // 0 .. MM*32-1
    int m = idx >> 5, q = (idx & 31) << 2;
    float4 v = *(const float4*)(x + (size_t)m * 128 + q);
    __half h[4];
    h[0] = __float2half(v.x); h[1] = __float2half(v.y);
    h[2] = __float2half(v.z); h[3] = __float2half(v.w);
    *(u64*)(g_Ah + (size_t)m * 192 + q) = *(u64*)h;
}

// ---------------------------------------------------------------------------
// Kernel P: both weight preps. idx < 73728: W12-fold -> g_Bp; else W11 -> g_B11
// ---------------------------------------------------------------------------
__global__ void k_prep(const float* __restrict__ W11, const float* __restrict__ W12)
{
    int t = blockIdx.x * 256 + threadIdx.x;
    if (t < 384 * 192) {
        int n = t / 192, k = t % 192;
        int p3 = (n / 3) * 3, j = n % 3;
        const float C   = 1098.9010989010989f;   // E/(1-nu^2)
        const float CNU = 329.67032967032966f;   // C*nu
        const float CSH = 384.61538461538464f;   // C*(1-nu)/2
        float w;
        if (j == 0)      w = C   * W12[(size_t)p3 * 192 + k] + CNU * W12[(size_t)(p3 + 1) * 192 + k];
        else if (j == 1) w = CNU * W12[(size_t)p3 * 192 + k] + C   * W12[(size_t)(p3 + 1) * 192 + k];
        else             w = CSH * W12[(size_t)n * 192 + k];
        g_Bp[t] = __float2half(w);
    } else {
        int i = t - 384 * 192;
        if (i < 128 * 128) g_B11[i] = __float2half(W11[i]);
    }
}

// ---------------------------------------------------------------------------
// Kernel A: fc11 mma.sync GEMM (exact R12/R14 config). grid (1024): BM=128,
//   BN=128, K=128 (4 stages). 8 warps 2Mx4N -> warp tile 64x32.
// ---------------------------------------------------------------------------
#define FC11_STG  20480
#define FC11_SMEM 61440

__global__ void __launch_bounds__(256, 1) k_fc11_mma(const float* __restrict__ b11)
{
    extern __shared__ char smem[];
    const uint32_t sb = smem_u32(smem);
    const int tid  = threadIdx.x;
    const int lane = tid & 31;
    const int w    = tid >> 5;
    const int wm   = w >> 2;            // 0..1
    const int wn   = w & 3;             // 0..3
    const int g    = lane >> 2;
    const int t4   = lane & 3;
    const int m0   = blockIdx.x << 7;

    __shared__ float b11s[128];
    if (tid < 128) b11s[tid] = b11[tid];

    float acc[4][4][4];
#pragma unroll
    for (int a = 0; a < 4; ++a)
#pragma unroll
        for (int b = 0; b < 4; ++b)
#pragma unroll
            for (int c = 0; c < 4; ++c) acc[a][b][c] = 0.f;

    const int lrow = tid >> 2, lch = tid & 3;

    auto issue = [&](int s) {
        const int kk0 = s << 5;
        uint32_t base = sb + (uint32_t)(s % 3) * FC11_STG;
#pragma unroll
        for (int i = 0; i < 2; ++i) {
            int row = lrow + (i << 6);
            cpasync16(base + row * APITCH + (lch << 4),
                      g_Ah + (size_t)(m0 + row) * 192 + kk0 + (lch << 3));
        }
#pragma unroll
        for (int i = 0; i < 2; ++i) {
            int row = lrow + (i << 6);
            cpasync16(base + 10240 + row * APITCH + (lch << 4),
                      g_B11 + (size_t)row * 128 + kk0 + (lch << 3));
        }
        cpcommit();
    };

    issue(0); issue(1);

    for (int s = 0; s < 4; ++s) {
        if (s < 3) { cpwait<1>(); } else { cpwait<0>(); }
        __syncthreads();
        if (s + 2 < 4) issue(s + 2);

        const uint32_t Ab = sb + (uint32_t)(s % 3) * FC11_STG;
        const uint32_t Bb = Ab + 10240u;
#pragma unroll
        for (int ks = 0; ks < 2; ++ks) {
            const int kk = ks << 4;
            uint32_t a[4][4];
#pragma unroll
            for (int mt = 0; mt < 4; ++mt) {
                int row = wm * 64 + mt * 16 + (lane & 15);
                ldsm_x4(a[mt][0], a[mt][1], a[mt][2], a[mt][3],
                        Ab + row * APITCH + ((kk + ((lane >> 4) << 3)) << 1));
            }
#pragma unroll
            for (int np = 0; np < 2; ++np) {
                int n = wn * 32 + np * 16 + ((lane >> 4) << 3) + (lane & 7);
                uint32_t b0, b1, b2, b3;
                ldsm_x4(b0, b1, b2, b3, Bb + n * APITCH + ((kk + (lane & 8)) << 1));
#pragma unroll
                for (int mt = 0; mt < 4; ++mt) {
                    mma16816(acc[mt][2*np][0], acc[mt][2*np][1], acc[mt][2*np][2], acc[mt][2*np][3],
                             a[mt][0], a[mt][1], a[mt][2], a[mt][3], b0, b1);
                    mma16816(acc[mt][2*np+1][0], acc[mt][2*np+1][1], acc[mt][2*np+1][2], acc[mt][2*np+1][3],
                             a[mt][0], a[mt][1], a[mt][2], a[mt][3], b2, b3);
                }
            }
        }
    }

    // epilogue: fragments hold (even,odd) col pairs -> dnew (fp16) directly
#pragma unroll
    for (int mt = 0; mt < 4; ++mt)
#pragma unroll
        for (int nn = 0; nn < 4; ++nn) {
            int n = wn * 32 + (nn >> 1) * 16 + (nn & 1) * 8 + 2 * t4;
            float be = b11s[n], bo = b11s[n + 1];
            int r0 = m0 + wm * 64 + mt * 16 + g;
#pragma unroll
            for (int hh = 0; hh < 2; ++hh) {
                float v0 = acc[mt][nn][2 * hh]     + be;
                float v1 = acc[mt][nn][2 * hh + 1] + bo;
                v0 = v0 > 0.f ? v0 : 0.01f * v0;
                v1 = v1 > 0.f ? v1 : 0.01f * v1;
                float jn = fmaxf(v0, 0.f);
                float delta = sqrtf(jn * jn + v1 * v1 + 1e-12f);
                float dn = __fdividef(0.1f * (delta - 0.01f),
                                      fmaxf(delta, 1e-12f) * 0.09f);
                dn = fminf(fmaxf(dn, 0.f), 1.f);
                g_dnew[(size_t)(r0 + 8 * hh) * 64 + (n >> 1)] = __float2half(dn);
            }
        }
}

// ---------------------------------------------------------------------------
// Kernel B: segmented prefix-max (exact R14). grid 256, 512 threads.
// ---------------------------------------------------------------------------
__global__ void __launch_bounds__(512, 2) k_prefixmax()
{
    __shared__ float segmax[8][64];
    const int b = blockIdx.x;
    const int p = threadIdx.x & 63;
    const int s = threadIdx.x >> 6;     // 0..7
    const __half* src = g_dnew + (size_t)b * 512 * 64 + (size_t)s * 64 * 64 + p;

    float mx = 0.f;
    for (int t0 = 0; t0 < 64; t0 += 8) {
        float v[8];
#pragma unroll
        for (int i = 0; i < 8; ++i) v[i] = __half2float(src[(size_t)(t0 + i) * 64]);
#pragma unroll
        for (int i = 0; i < 8; ++i) mx = fmaxf(mx, v[i]);
    }
    segmax[s][p] = mx;
    __syncthreads();

    float run = 0.f;
#pragma unroll
    for (int ss = 0; ss < 7; ++ss)
        if (ss < s) run = fmaxf(run, segmax[ss][p]);

    __half* dh = g_Ah + (size_t)b * 512 * 192 + (size_t)s * 64 * 192 + 128 + p;
    for (int t0 = 0; t0 < 64; t0 += 8) {
        float v[8];
#pragma unroll
        for (int i = 0; i < 8; ++i) v[i] = __half2float(src[(size_t)(t0 + i) * 64]);
#pragma unroll
        for (int i = 0; i < 8; ++i) {
            run = fmaxf(run, v[i]);
            dh[(size_t)(t0 + i) * 192] = __float2half(run);
        }
    }
}

// ---------------------------------------------------------------------------
// Kernel C: fc12 mma.sync GEMM. grid (4, 1024): x = N-tile (adjacent CTAs
//   share A via L2), y = m-tile. BM=128, BN=96, K=192 (6 stages).
//   3-buffer cp.async, 256 thr, warp grid 4Mx2N: warp tile 32x48, 2 CTA/SM.
//   R16 change: epilogue via smem slab [128][104] half -> coalesced stores.
// ---------------------------------------------------------------------------
#define FC12_STG  17920
#define FC12_SMEM 53760

__global__ void __launch_bounds__(256, 2) k_fc12_mma()
{
    extern __shared__ char smem[];
    const uint32_t sb = smem_u32(smem);
    const int tid  = threadIdx.x;
    const int lane = tid & 31;
    const int w    = tid >> 5;
    const int wm   = w >> 1;
    const int wn   = w & 1;
    const int g    = lane >> 2;
    const int t4   = lane & 3;
    const int gy   = blockIdx.x;          // n-tile: cols gy*96..
    const int m0   = blockIdx.y << 7;

    float acc[2][6][4];
#pragma unroll
    for (int a = 0; a < 2; ++a)
#pragma unroll
        for (int b = 0; b < 6; ++b)
#pragma unroll
            for (int c = 0; c < 4; ++c) acc[a][b][c] = 0.f;

    const int lrow = tid >> 2, lch = tid & 3;

    auto issue = [&](int s) {
        const int kk0 = s << 5;
        uint32_t base = sb + (uint32_t)(s % 3) * FC12_STG;
#pragma unroll
        for (int i = 0; i < 2; ++i) {
            int row = lrow + (i << 6);
            cpasync16(base + row * APITCH + (lch << 4),
                      g_Ah + (size_t)(m0 + row) * 192 + kk0 + (lch << 3));
        }
#pragma unroll
        for (int i = 0; i < 2; ++i) {
            int id = tid + (i << 8);
            if (id < 384) {
                int row = id >> 2, c = id & 3;
                cpasync16(base + 10240 + row * APITCH + (c << 4),
                          g_Bp + (size_t)(gy * 96 + row) * 192 + kk0 + (c << 3));
            }
        }
        cpcommit();
    };

    issue(0); issue(1);

    for (int s = 0; s < 6; ++s) {
        if (s < 5) { cpwait<1>(); } else { cpwait<0>(); }
        __syncthreads();
        if (s + 2 < 6) issue(s + 2);

        const uint32_t Ab = sb + (uint32_t)(s % 3) * FC12_STG;
        const uint32_t Bb = Ab + 10240u;
#pragma unroll
        for (int ks = 0; ks < 2; ++ks) {
            const int kk = ks << 4;
            uint32_t a[2][4];
#pragma unroll
            for (int mt = 0; mt < 2; ++mt) {
                int row = wm * 32 + mt * 16 + (lane & 15);
                ldsm_x4(a[mt][0], a[mt][1], a[mt][2], a[mt][3],
                        Ab + row * APITCH + ((kk + ((lane >> 4) << 3)) << 1));
            }
#pragma unroll
            for (int np = 0; np < 3; ++np) {
                int n = wn * 48 + np * 16 + ((lane >> 4) << 3) + (lane & 7);
                uint32_t b0, b1, b2, b3;
                ldsm_x4(b0, b1, b2, b3, Bb + n * APITCH + ((kk + (lane & 8)) << 1));
#pragma unroll
                for (int mt = 0; mt < 2; ++mt) {
                    mma16816(acc[mt][2*np][0], acc[mt][2*np][1], acc[mt][2*np][2], acc[mt][2*np][3],
                             a[mt][0], a[mt][1], a[mt][2], a[mt][3], b0, b1);
                    mma16816(acc[mt][2*np+1][0], acc[mt][2*np+1][1], acc[mt][2*np+1][2], acc[mt][2*np+1][3],
                             a[mt][0], a[mt][1], a[mt][2], a[mt][3], b2, b3);
                }
            }
        }
    }

    // ------- epilogue: slab (bit-identical half2 values) + coalesced stores -------
    __syncthreads();                       // mainloop smem reads complete
    __half* slab = (__half*)smem;          // [128][104] half = 26624 B
#pragma unroll
    for (int mt = 0; mt < 2; ++mt) {
        int row = wm * 32 + mt * 16 + g;   // 0..127 local
#pragma unroll
        for (int j = 0; j < 6; ++j) {
            int col = wn * 48 + (j >> 1) * 16 + (j & 1) * 8 + 2 * t4;
            *(__half2*)&slab[row * 104 + col]       = __floats2half2_rn(acc[mt][j][0], acc[mt][j][1]);
            *(__half2*)&slab[(row + 8) * 104 + col] = __floats2half2_rn(acc[mt][j][2], acc[mt][j][3]);
        }
    }
    __syncthreads();
    // each row = 96 halves = 12 x 16B chunks; 128 rows x 12 = 1536 chunks
    for (int i = tid; i < 1536; i += 256) {
        int r = i / 12, c = i - r * 12;
        *(uint4*)&g_strain[(size_t)(m0 + r) * 384 + gy * 96 + (c << 3)] =
            *(uint4*)&slab[r * 104 + (c << 3)];
    }
}

// ---------------------------------------------------------------------------
// Kernel T: fused tail (exact R14 config). One CTA per batch b (256 CTAs,
//   128 threads). Per 32-t chunk: load fp16 sig -> f32 smem, seq + J2 chain,
//   GEMV + softplus -> out.
// ---------------------------------------------------------------------------
#define TAIL_SMEM (12288 + 49664)   // w2t [384][8] f32 + gs [32][388] f32

__global__ void __launch_bounds__(128, 3) k_tail(const float* __restrict__ W2,
                                                 float* __restrict__ out)
{
    extern __shared__ float ts[];
    float* w2t = ts;            // [384][8]
    float* gs  = ts + 3072;     // [32][388]
    const int tid = threadIdx.x;
    const int b   = blockIdx.x;

    for (int i = tid; i < 2304; i += 128) {
        int o = i / 384, k = i - o * 384;
        w2t[k * 8 + o] = W2[i];
    }

    const float SY = 10.f, H = 100.f;
    const float INV = (float)(1.0 / (3.0 * (1000.0 / 2.6) + 100.0));
    float ep = 0.f;
    const __half* sigb = g_strain + (size_t)b * 512 * 384;
    const int tlb = tid >> 2, q = tid & 3;
    const int p = tid;

    for (int chunk = 0; chunk < 16; ++chunk) {
        __syncthreads();
        const __half* src = sigb + (size_t)chunk * 32 * 384;
        for (int i = tid; i < 1536; i += 128) {
            int tl = i / 48, c8 = i - tl * 48;
            uint4 raw = *(const uint4*)(src + tl * 384 + (c8 << 3));
            float2 f0 = __half22float2(*(__half2*)&raw.x);
            float2 f1 = __half22float2(*(__half2*)&raw.y);
            float2 f2 = __half22float2(*(__half2*)&raw.z);
            float2 f3 = __half22float2(*(__half2*)&raw.w);
            float* dst = &gs[tl * 388 + (c8 << 3)];
            dst[0] = f0.x; dst[1] = f0.y; dst[2] = f1.x; dst[3] = f1.y;
            dst[4] = f2.x; dst[5] = f2.y; dst[6] = f3.x; dst[7] = f3.y;
        }
        __syncthreads();
#pragma unroll 4
        for (int tl = 0; tl < 32; ++tl) {
            float* row = gs + tl * 388 + 3 * p;
            float s0 = row[0], s1 = row[1], s2 = row[2];
            float seq = sqrtf(s0 * s0 - s0 * s1 + s1 * s1 + 3.f * s2 * s2 + 1e-12f);
            float fy = seq - fmaf(H, ep, SY);
            float sc;
            if (fy > 0.f) {
                ep = fmaf(fy, INV, ep);
                sc = __fdividef(fmaf(H, ep, SY), seq);
            } else {
                sc = 1.f;
            }
            row[0] = sc * s0; row[1] = sc * s1; row[2] = sc * s2;
        }
        __syncthreads();
        float acc[6] = {0.f, 0.f, 0.f, 0.f, 0.f, 0.f};
        const float* grow = gs + tlb * 388;
#pragma unroll 8
        for (int i = 0; i < 96; ++i) {
            int k = (i << 2) + q;
            float gv = grow[k];
            float4 wa = *(float4*)&w2t[k * 8];
            float2 wb = *(float2*)&w2t[k * 8 + 4];
            acc[0] = fmaf(gv, wa.x, acc[0]);
            acc[1] = fmaf(gv, wa.y, acc[1]);
            acc[2] = fmaf(gv, wa.z, acc[2]);
            acc[3] = fmaf(gv, wa.w, acc[3]);
            acc[4] = fmaf(gv, wb.x, acc[4]);
            acc[5] = fmaf(gv, wb.y, acc[5]);
        }
#pragma unroll
        for (int o = 0; o < 6; ++o) {
            acc[o] += __shfl_xor_sync(0xffffffffu, acc[o], 1);
            acc[o] += __shfl_xor_sync(0xffffffffu, acc[o], 2);
        }
        if (q == 0) {
            int t = chunk * 32 + tlb;
            float* op = out + ((size_t)b * 512 + t) * 6;
#pragma unroll
            for (int o = 0; o < 6; ++o) {
                float v = acc[o];
                op[o] = fmaxf(v, 0.f) + log1pf(expf(-fabsf(v)));
            }
        }
    }
}

// ---------------------------------------------------------------------------
extern "C" void kernel_launch(void* const* d_in, const int* in_sizes, int n_in,
                              void* d_out, int out_size)
{
    const float* x   = (const float*)d_in[0];
    const float* W11 = (const float*)d_in[1];
    const float* b11 = (const float*)d_in[2];
    const float* W12 = (const float*)d_in[3];
    const float* W2  = (const float*)d_in[4];
    float* out = (float*)d_out;

    (void)in_sizes; (void)n_in; (void)out_size;

    cudaFuncSetAttribute(k_fc11_mma, cudaFuncAttributeMaxDynamicSharedMemorySize, FC11_SMEM);
    cudaFuncSetAttribute(k_fc12_mma, cudaFuncAttributeMaxDynamicSharedMemorySize, FC12_SMEM);
    cudaFuncSetAttribute(k_tail,     cudaFuncAttributeMaxDynamicSharedMemorySize, TAIL_SMEM);

    k_splitx<<<MM / 8, 256>>>(x);
    k_prep<<<352, 256>>>(W11, W12);
    k_fc11_mma<<<MM / 128, 256, FC11_SMEM>>>(b11);
    k_prefixmax<<<256, 512>>>();
    k_fc12_mma<<<dim3(4, MM / 128), 256, FC12_SMEM>>>();
    k_tail<<<256, 128, TAIL_SMEM>>>(W2, out);
}

// round 17
// speedup vs baseline: 1.1018x; 1.0135x over previous
#include <cuda_runtime.h>
#include <cuda_fp16.h>
#include <cstdint>

// ---------------------------------------------------------------------------
// Pipeline (plain fp16 GEMMs + fp16 intermediates; error ~3.3e-4 vs 1e-3):
//   S : x -> fp16                        -> g_Ah [M,192] cols 0..127
//   P : W11 -> fp16; fold D into W12 -> fp16  (one kernel)
//   A : fc11 mma.sync GEMM (K=128) + dnew -> g_dnew [M,64] fp16
//   B : segmented prefix-max over T -> dmg fp16 -> g_Ah cols 128..191
//   C : fc12 mma.sync GEMM (K=192) + slab epilogue -> g_strain fp16 [M,384]
//   T : fused seq + J2 scan + fc2 + softplus -> out
// R17: exact R16 + ONE change: tail ep-phase restructured (batch the
// chain-independent sqrts; keep the recurrence to cheap fmaf/cmp ops).
// Bit-identical arithmetic.
// ---------------------------------------------------------------------------

typedef unsigned long long u64;

#define MM 131072   // 256*512

__device__ __align__(16) __half g_dnew[(size_t)MM * 64];
__device__ __align__(16) __half g_strain[(size_t)MM * 384];
__device__ __align__(16) __half g_Ah[(size_t)MM * 192];
__device__ __align__(16) __half g_Bp[384 * 192];
__device__ __align__(16) __half g_B11[128 * 128];

__device__ __forceinline__ uint32_t smem_u32(const void* p) {
    uint32_t a;
    asm("{ .reg .u64 t; cvta.to.shared.u64 t, %1; cvt.u32.u64 %0, t; }" : "=r"(a) : "l"(p));
    return a;
}
__device__ __forceinline__ void cpasync16(uint32_t dst, const void* src) {
    asm volatile("cp.async.ca.shared.global [%0], [%1], 16;" :: "r"(dst), "l"(src) : "memory");
}
__device__ __forceinline__ void cpcommit() {
    asm volatile("cp.async.commit_group;" ::: "memory");
}
template <int N>
__device__ __forceinline__ void cpwait() {
    asm volatile("cp.async.wait_group %0;" :: "n"(N) : "memory");
}
__device__ __forceinline__ void ldsm_x4(uint32_t& r0, uint32_t& r1, uint32_t& r2,
                                        uint32_t& r3, uint32_t addr) {
    asm volatile("ldmatrix.sync.aligned.m8n8.x4.shared.b16 {%0,%1,%2,%3}, [%4];"
                 : "=r"(r0), "=r"(r1), "=r"(r2), "=r"(r3) : "r"(addr));
}
__device__ __forceinline__ void mma16816(float& c0, float& c1, float& c2, float& c3,
                                         uint32_t a0, uint32_t a1, uint32_t a2, uint32_t a3,
                                         uint32_t b0, uint32_t b1) {
    asm volatile("mma.sync.aligned.m16n8k16.row.col.f32.f16.f16.f32 "
                 "{%0,%1,%2,%3}, {%4,%5,%6,%7}, {%8,%9}, {%0,%1,%2,%3};"
                 : "+f"(c0), "+f"(c1), "+f"(c2), "+f"(c3)
                 : "r"(a0), "r"(a1), "r"(a2), "r"(a3), "r"(b0), "r"(b1));
}

#define APITCH 80   // smem row pitch: 64B data + 16B pad (conflict-free ldsm)

// ---------------------------------------------------------------------------
// Kernel S: x -> fp16 -> g_Ah cols [0,128)
// ---------------------------------------------------------------------------
__global__ void k_splitx(const float* __restrict__ x)
{
    int idx = blockIdx.x * 256 + threadIdx.x;     // 0 .. MM*32-1
    int m = idx >> 5, q = (idx & 31) << 2;
    float4 v = *(const float4*)(x + (size_t)m * 128 + q);
    __half h[4];
    h[0] = __float2half(v.x); h[1] = __float2half(v.y);
    h[2] = __float2half(v.z); h[3] = __float2half(v.w);
    *(u64*)(g_Ah + (size_t)m * 192 + q) = *(u64*)h;
}

// ---------------------------------------------------------------------------
// Kernel P: both weight preps. idx < 73728: W12-fold -> g_Bp; else W11 -> g_B11
// ---------------------------------------------------------------------------
__global__ void k_prep(const float* __restrict__ W11, const float* __restrict__ W12)
{
    int t = blockIdx.x * 256 + threadIdx.x;
    if (t < 384 * 192) {
        int n = t / 192, k = t % 192;
        int p3 = (n / 3) * 3, j = n % 3;
        const float C   = 1098.9010989010989f;   // E/(1-nu^2)
        const float CNU = 329.67032967032966f;   // C*nu
        const float CSH = 384.61538461538464f;   // C*(1-nu)/2
        float w;
        if (j == 0)      w = C   * W12[(size_t)p3 * 192 + k] + CNU * W12[(size_t)(p3 + 1) * 192 + k];
        else if (j == 1) w = CNU * W12[(size_t)p3 * 192 + k] + C   * W12[(size_t)(p3 + 1) * 192 + k];
        else             w = CSH * W12[(size_t)n * 192 + k];
        g_Bp[t] = __float2half(w);
    } else {
        int i = t - 384 * 192;
        if (i < 128 * 128) g_B11[i] = __float2half(W11[i]);
    }
}

// ---------------------------------------------------------------------------
// Kernel A: fc11 mma.sync GEMM (exact R12/R14/R16 config). grid (1024):
//   BM=128, BN=128, K=128 (4 stages). 8 warps 2Mx4N -> warp tile 64x32.
// ---------------------------------------------------------------------------
#define FC11_STG  20480
#define FC11_SMEM 61440

__global__ void __launch_bounds__(256, 1) k_fc11_mma(const float* __restrict__ b11)
{
    extern __shared__ char smem[];
    const uint32_t sb = smem_u32(smem);
    const int tid  = threadIdx.x;
    const int lane = tid & 31;
    const int w    = tid >> 5;
    const int wm   = w >> 2;            // 0..1
    const int wn   = w & 3;             // 0..3
    const int g    = lane >> 2;
    const int t4   = lane & 3;
    const int m0   = blockIdx.x << 7;

    __shared__ float b11s[128];
    if (tid < 128) b11s[tid] = b11[tid];

    float acc[4][4][4];
#pragma unroll
    for (int a = 0; a < 4; ++a)
#pragma unroll
        for (int b = 0; b < 4; ++b)
#pragma unroll
            for (int c = 0; c < 4; ++c) acc[a][b][c] = 0.f;

    const int lrow = tid >> 2, lch = tid & 3;

    auto issue = [&](int s) {
        const int kk0 = s << 5;
        uint32_t base = sb + (uint32_t)(s % 3) * FC11_STG;
#pragma unroll
        for (int i = 0; i < 2; ++i) {
            int row = lrow + (i << 6);
            cpasync16(base + row * APITCH + (lch << 4),
                      g_Ah + (size_t)(m0 + row) * 192 + kk0 + (lch << 3));
        }
#pragma unroll
        for (int i = 0; i < 2; ++i) {
            int row = lrow + (i << 6);
            cpasync16(base + 10240 + row * APITCH + (lch << 4),
                      g_B11 + (size_t)row * 128 + kk0 + (lch << 3));
        }
        cpcommit();
    };

    issue(0); issue(1);

    for (int s = 0; s < 4; ++s) {
        if (s < 3) { cpwait<1>(); } else { cpwait<0>(); }
        __syncthreads();
        if (s + 2 < 4) issue(s + 2);

        const uint32_t Ab = sb + (uint32_t)(s % 3) * FC11_STG;
        const uint32_t Bb = Ab + 10240u;
#pragma unroll
        for (int ks = 0; ks < 2; ++ks) {
            const int kk = ks << 4;
            uint32_t a[4][4];
#pragma unroll
            for (int mt = 0; mt < 4; ++mt) {
                int row = wm * 64 + mt * 16 + (lane & 15);
                ldsm_x4(a[mt][0], a[mt][1], a[mt][2], a[mt][3],
                        Ab + row * APITCH + ((kk + ((lane >> 4) << 3)) << 1));
            }
#pragma unroll
            for (int np = 0; np < 2; ++np) {
                int n = wn * 32 + np * 16 + ((lane >> 4) << 3) + (lane & 7);
                uint32_t b0, b1, b2, b3;
                ldsm_x4(b0, b1, b2, b3, Bb + n * APITCH + ((kk + (lane & 8)) << 1));
#pragma unroll
                for (int mt = 0; mt < 4; ++mt) {
                    mma16816(acc[mt][2*np][0], acc[mt][2*np][1], acc[mt][2*np][2], acc[mt][2*np][3],
                             a[mt][0], a[mt][1], a[mt][2], a[mt][3], b0, b1);
                    mma16816(acc[mt][2*np+1][0], acc[mt][2*np+1][1], acc[mt][2*np+1][2], acc[mt][2*np+1][3],
                             a[mt][0], a[mt][1], a[mt][2], a[mt][3], b2, b3);
                }
            }
        }
    }

    // epilogue: fragments hold (even,odd) col pairs -> dnew (fp16) directly
#pragma unroll
    for (int mt = 0; mt < 4; ++mt)
#pragma unroll
        for (int nn = 0; nn < 4; ++nn) {
            int n = wn * 32 + (nn >> 1) * 16 + (nn & 1) * 8 + 2 * t4;
            float be = b11s[n], bo = b11s[n + 1];
            int r0 = m0 + wm * 64 + mt * 16 + g;
#pragma unroll
            for (int hh = 0; hh < 2; ++hh) {
                float v0 = acc[mt][nn][2 * hh]     + be;
                float v1 = acc[mt][nn][2 * hh + 1] + bo;
                v0 = v0 > 0.f ? v0 : 0.01f * v0;
                v1 = v1 > 0.f ? v1 : 0.01f * v1;
                float jn = fmaxf(v0, 0.f);
                float delta = sqrtf(jn * jn + v1 * v1 + 1e-12f);
                float dn = __fdividef(0.1f * (delta - 0.01f),
                                      fmaxf(delta, 1e-12f) * 0.09f);
                dn = fminf(fmaxf(dn, 0.f), 1.f);
                g_dnew[(size_t)(r0 + 8 * hh) * 64 + (n >> 1)] = __float2half(dn);
            }
        }
}

// ---------------------------------------------------------------------------
// Kernel B: segmented prefix-max (exact R14). grid 256, 512 threads.
// ---------------------------------------------------------------------------
__global__ void __launch_bounds__(512, 2) k_prefixmax()
{
    __shared__ float segmax[8][64];
    const int b = blockIdx.x;
    const int p = threadIdx.x & 63;
    const int s = threadIdx.x >> 6;     // 0..7
    const __half* src = g_dnew + (size_t)b * 512 * 64 + (size_t)s * 64 * 64 + p;

    float mx = 0.f;
    for (int t0 = 0; t0 < 64; t0 += 8) {
        float v[8];
#pragma unroll
        for (int i = 0; i < 8; ++i) v[i] = __half2float(src[(size_t)(t0 + i) * 64]);
#pragma unroll
        for (int i = 0; i < 8; ++i) mx = fmaxf(mx, v[i]);
    }
    segmax[s][p] = mx;
    __syncthreads();

    float run = 0.f;
#pragma unroll
    for (int ss = 0; ss < 7; ++ss)
        if (ss < s) run = fmaxf(run, segmax[ss][p]);

    __half* dh = g_Ah + (size_t)b * 512 * 192 + (size_t)s * 64 * 192 + 128 + p;
    for (int t0 = 0; t0 < 64; t0 += 8) {
        float v[8];
#pragma unroll
        for (int i = 0; i < 8; ++i) v[i] = __half2float(src[(size_t)(t0 + i) * 64]);
#pragma unroll
        for (int i = 0; i < 8; ++i) {
            run = fmaxf(run, v[i]);
            dh[(size_t)(t0 + i) * 192] = __float2half(run);
        }
    }
}

// ---------------------------------------------------------------------------
// Kernel C: fc12 mma.sync GEMM (exact R16 config). grid (4, 1024): x = N-tile
//   (adjacent CTAs share A via L2), y = m-tile. BM=128, BN=96, K=192.
//   3-buffer cp.async, warp tile 32x48, 2 CTA/SM, slab epilogue.
// ---------------------------------------------------------------------------
#define FC12_STG  17920
#define FC12_SMEM 53760

__global__ void __launch_bounds__(256, 2) k_fc12_mma()
{
    extern __shared__ char smem[];
    const uint32_t sb = smem_u32(smem);
    const int tid  = threadIdx.x;
    const int lane = tid & 31;
    const int w    = tid >> 5;
    const int wm   = w >> 1;
    const int wn   = w & 1;
    const int g    = lane >> 2;
    const int t4   = lane & 3;
    const int gy   = blockIdx.x;          // n-tile: cols gy*96..
    const int m0   = blockIdx.y << 7;

    float acc[2][6][4];
#pragma unroll
    for (int a = 0; a < 2; ++a)
#pragma unroll
        for (int b = 0; b < 6; ++b)
#pragma unroll
            for (int c = 0; c < 4; ++c) acc[a][b][c] = 0.f;

    const int lrow = tid >> 2, lch = tid & 3;

    auto issue = [&](int s) {
        const int kk0 = s << 5;
        uint32_t base = sb + (uint32_t)(s % 3) * FC12_STG;
#pragma unroll
        for (int i = 0; i < 2; ++i) {
            int row = lrow + (i << 6);
            cpasync16(base + row * APITCH + (lch << 4),
                      g_Ah + (size_t)(m0 + row) * 192 + kk0 + (lch << 3));
        }
#pragma unroll
        for (int i = 0; i < 2; ++i) {
            int id = tid + (i << 8);
            if (id < 384) {
                int row = id >> 2, c = id & 3;
                cpasync16(base + 10240 + row * APITCH + (c << 4),
                          g_Bp + (size_t)(gy * 96 + row) * 192 + kk0 + (c << 3));
            }
        }
        cpcommit();
    };

    issue(0); issue(1);

    for (int s = 0; s < 6; ++s) {
        if (s < 5) { cpwait<1>(); } else { cpwait<0>(); }
        __syncthreads();
        if (s + 2 < 6) issue(s + 2);

        const uint32_t Ab = sb + (uint32_t)(s % 3) * FC12_STG;
        const uint32_t Bb = Ab + 10240u;
#pragma unroll
        for (int ks = 0; ks < 2; ++ks) {
            const int kk = ks << 4;
            uint32_t a[2][4];
#pragma unroll
            for (int mt = 0; mt < 2; ++mt) {
                int row = wm * 32 + mt * 16 + (lane & 15);
                ldsm_x4(a[mt][0], a[mt][1], a[mt][2], a[mt][3],
                        Ab + row * APITCH + ((kk + ((lane >> 4) << 3)) << 1));
            }
#pragma unroll
            for (int np = 0; np < 3; ++np) {
                int n = wn * 48 + np * 16 + ((lane >> 4) << 3) + (lane & 7);
                uint32_t b0, b1, b2, b3;
                ldsm_x4(b0, b1, b2, b3, Bb + n * APITCH + ((kk + (lane & 8)) << 1));
#pragma unroll
                for (int mt = 0; mt < 2; ++mt) {
                    mma16816(acc[mt][2*np][0], acc[mt][2*np][1], acc[mt][2*np][2], acc[mt][2*np][3],
                             a[mt][0], a[mt][1], a[mt][2], a[mt][3], b0, b1);
                    mma16816(acc[mt][2*np+1][0], acc[mt][2*np+1][1], acc[mt][2*np+1][2], acc[mt][2*np+1][3],
                             a[mt][0], a[mt][1], a[mt][2], a[mt][3], b2, b3);
                }
            }
        }
    }

    // ------- epilogue: slab (bit-identical half2 values) + coalesced stores -------
    __syncthreads();
    __half* slab = (__half*)smem;          // [128][104] half = 26624 B
#pragma unroll
    for (int mt = 0; mt < 2; ++mt) {
        int row = wm * 32 + mt * 16 + g;
#pragma unroll
        for (int j = 0; j < 6; ++j) {
            int col = wn * 48 + (j >> 1) * 16 + (j & 1) * 8 + 2 * t4;
            *(__half2*)&slab[row * 104 + col]       = __floats2half2_rn(acc[mt][j][0], acc[mt][j][1]);
            *(__half2*)&slab[(row + 8) * 104 + col] = __floats2half2_rn(acc[mt][j][2], acc[mt][j][3]);
        }
    }
    __syncthreads();
    for (int i = tid; i < 1536; i += 256) {
        int r = i / 12, c = i - r * 12;
        *(uint4*)&g_strain[(size_t)(m0 + r) * 384 + gy * 96 + (c << 3)] =
            *(uint4*)&slab[r * 104 + (c << 3)];
    }
}

// ---------------------------------------------------------------------------
// Kernel T: fused tail. One CTA per batch b (256 CTAs, 128 threads).
//   R17 change: ep phase batches the chain-independent sqrts (8 at a time),
//   recurrence reduced to fmaf/cmp; divide off the critical path.
// ---------------------------------------------------------------------------
#define TAIL_SMEM (12288 + 49664)   // w2t [384][8] f32 + gs [32][388] f32

__global__ void __launch_bounds__(128, 3) k_tail(const float* __restrict__ W2,
                                                 float* __restrict__ out)
{
    extern __shared__ float ts[];
    float* w2t = ts;            // [384][8]
    float* gs  = ts + 3072;     // [32][388]
    const int tid = threadIdx.x;
    const int b   = blockIdx.x;

    for (int i = tid; i < 2304; i += 128) {
        int o = i / 384, k = i - o * 384;
        w2t[k * 8 + o] = W2[i];
    }

    const float SY = 10.f, H = 100.f;
    const float INV = (float)(1.0 / (3.0 * (1000.0 / 2.6) + 100.0));
    float ep = 0.f;
    const __half* sigb = g_strain + (size_t)b * 512 * 384;
    const int tlb = tid >> 2, q = tid & 3;
    const int p = tid;

    for (int chunk = 0; chunk < 16; ++chunk) {
        __syncthreads();
        const __half* src = sigb + (size_t)chunk * 32 * 384;
        for (int i = tid; i < 1536; i += 128) {
            int tl = i / 48, c8 = i - tl * 48;
            uint4 raw = *(const uint4*)(src + tl * 384 + (c8 << 3));
            float2 f0 = __half22float2(*(__half2*)&raw.x);
            float2 f1 = __half22float2(*(__half2*)&raw.y);
            float2 f2 = __half22float2(*(__half2*)&raw.z);
            float2 f3 = __half22float2(*(__half2*)&raw.w);
            float* dst = &gs[tl * 388 + (c8 << 3)];
            dst[0] = f0.x; dst[1] = f0.y; dst[2] = f1.x; dst[3] = f1.y;
            dst[4] = f2.x; dst[5] = f2.y; dst[6] = f3.x; dst[7] = f3.y;
        }
        __syncthreads();
        // ep phase: batch 8 independent seq (sqrt pipelines), then the cheap
        // recurrence; the scale divide hangs off the chain. Bit-identical math.
#pragma unroll
        for (int tl0 = 0; tl0 < 32; tl0 += 8) {
            float sq[8];
#pragma unroll
            for (int i = 0; i < 8; ++i) {
                const float* row = gs + (tl0 + i) * 388 + 3 * p;
                float s0 = row[0], s1 = row[1], s2 = row[2];
                sq[i] = sqrtf(s0 * s0 - s0 * s1 + s1 * s1 + 3.f * s2 * s2 + 1e-12f);
            }
#pragma unroll
            for (int i = 0; i < 8; ++i) {
                float fy = sq[i] - fmaf(H, ep, SY);
                float sc;
                if (fy > 0.f) {
                    ep = fmaf(fy, INV, ep);
                    sc = __fdividef(fmaf(H, ep, SY), sq[i]);
                } else {
                    sc = 1.f;
                }
                float* row = gs + (tl0 + i) * 388 + 3 * p;
                float s0 = row[0], s1 = row[1], s2 = row[2];
                row[0] = sc * s0; row[1] = sc * s1; row[2] = sc * s2;
            }
        }
        __syncthreads();
        float acc[6] = {0.f, 0.f, 0.f, 0.f, 0.f, 0.f};
        const float* grow = gs + tlb * 388;
#pragma unroll 8
        for (int i = 0; i < 96; ++i) {
            int k = (i << 2) + q;
            float gv = grow[k];
            float4 wa = *(float4*)&w2t[k * 8];
            float2 wb = *(float2*)&w2t[k * 8 + 4];
            acc[0] = fmaf(gv, wa.x, acc[0]);
            acc[1] = fmaf(gv, wa.y, acc[1]);
            acc[2] = fmaf(gv, wa.z, acc[2]);
            acc[3] = fmaf(gv, wa.w, acc[3]);
            acc[4] = fmaf(gv, wb.x, acc[4]);
            acc[5] = fmaf(gv, wb.y, acc[5]);
        }
#pragma unroll
        for (int o = 0; o < 6; ++o) {
            acc[o] += __shfl_xor_sync(0xffffffffu, acc[o], 1);
            acc[o] += __shfl_xor_sync(0xffffffffu, acc[o], 2);
        }
        if (q == 0) {
            int t = chunk * 32 + tlb;
            float* op = out + ((size_t)b * 512 + t) * 6;
#pragma unroll
            for (int o = 0; o < 6; ++o) {
                float v = acc[o];
                op[o] = fmaxf(v, 0.f) + log1pf(expf(-fabsf(v)));
            }
        }
    }
}

// ---------------------------------------------------------------------------
extern "C" void kernel_launch(void* const* d_in, const int* in_sizes, int n_in,
                              void* d_out, int out_size)
{
    const float* x   = (const float*)d_in[0];
    const float* W11 = (const float*)d_in[1];
    const float* b11 = (const float*)d_in[2];
    const float* W12 = (const float*)d_in[3];
    const float* W2  = (const float*)d_in[4];
    float* out = (float*)d_out;

    (void)in_sizes; (void)n_in; (void)out_size;

    cudaFuncSetAttribute(k_fc11_mma, cudaFuncAttributeMaxDynamicSharedMemorySize, FC11_SMEM);
    cudaFuncSetAttribute(k_fc12_mma, cudaFuncAttributeMaxDynamicSharedMemorySize, FC12_SMEM);
    cudaFuncSetAttribute(k_tail,     cudaFuncAttributeMaxDynamicSharedMemorySize, TAIL_SMEM);

    k_splitx<<<MM / 8, 256>>>(x);
    k_prep<<<352, 256>>>(W11, W12);
    k_fc11_mma<<<MM / 128, 256, FC11_SMEM>>>(b11);
    k_prefixmax<<<256, 512>>>();
    k_fc12_mma<<<dim3(4, MM / 128), 256, FC12_SMEM>>>();
    k_tail<<<256, 128, TAIL_SMEM>>>(W2, out);
}